// round 1
// baseline (speedup 1.0000x reference)
#include <cuda_runtime.h>
#include <cstddef>

#define D_MODEL 1024
#define NHEADS  16
#define HD      64
#define BATCH   2
#define TSEQ    2048
#define MROWS   (BATCH*TSEQ)   /* 4096 */

// Scratch buffers (device globals: no allocations allowed)
__device__ float g_q[(size_t)MROWS * D_MODEL];     // [B,H,T,64]
__device__ float g_k[(size_t)MROWS * D_MODEL];     // [B,H,T,64]
__device__ float g_v[(size_t)MROWS * D_MODEL];     // [B,H,T,64]
__device__ float g_attn[(size_t)MROWS * D_MODEL];  // [B,T,1024]

// ---------------------------------------------------------------------------
// SGEMM: C = A @ B^T   (A: [4096,1024] row-major, B: [1024,1024] row-major)
// 128x128x8 tiles, 256 threads, 8x8 per-thread register tile.
// PERMUTE=1: write C[r][c] to [B,H,T,64] layout (c -> h*64+d, r -> b*T+t).
// ---------------------------------------------------------------------------
template <int PERMUTE>
__device__ __forceinline__ void gemm_body(const float* __restrict__ A,
                                          const float* __restrict__ Bm,
                                          float* __restrict__ C)
{
    __shared__ float As[8][128];
    __shared__ float Bs[8][128];

    const int tid = threadIdx.x;
    const int tx  = tid & 15;    // col group
    const int ty  = tid >> 4;    // row group
    const int bx  = blockIdx.x;  // N tile (0..7)
    const int by  = blockIdx.y;  // M tile (0..31)

    const int lr = tid >> 1;        // 0..127 tile row for global load
    const int lc = (tid & 1) << 2;  // 0 or 4

    const float* Ab = A  + ((size_t)(by * 128 + lr)) * 1024 + lc;
    const float* Bb = Bm + ((size_t)(bx * 128 + lr)) * 1024 + lc;

    float acc[8][8];
#pragma unroll
    for (int i = 0; i < 8; i++)
#pragma unroll
        for (int j = 0; j < 8; j++) acc[i][j] = 0.f;

    for (int k0 = 0; k0 < 1024; k0 += 8) {
        const float4 av = *(const float4*)(Ab + k0);
        const float4 bv = *(const float4*)(Bb + k0);
        __syncthreads();   // previous iteration's compute done before overwrite
        As[lc + 0][lr] = av.x; As[lc + 1][lr] = av.y;
        As[lc + 2][lr] = av.z; As[lc + 3][lr] = av.w;
        Bs[lc + 0][lr] = bv.x; Bs[lc + 1][lr] = bv.y;
        Bs[lc + 2][lr] = bv.z; Bs[lc + 3][lr] = bv.w;
        __syncthreads();
#pragma unroll
        for (int kk = 0; kk < 8; kk++) {
            float a[8], b[8];
            *(float4*)(a)     = *(const float4*)(&As[kk][ty * 4]);
            *(float4*)(a + 4) = *(const float4*)(&As[kk][64 + ty * 4]);
            *(float4*)(b)     = *(const float4*)(&Bs[kk][tx * 4]);
            *(float4*)(b + 4) = *(const float4*)(&Bs[kk][64 + tx * 4]);
#pragma unroll
            for (int i = 0; i < 8; i++)
#pragma unroll
                for (int j = 0; j < 8; j++)
                    acc[i][j] = fmaf(a[i], b[j], acc[i][j]);
        }
    }

#pragma unroll
    for (int i = 0; i < 8; i++) {
        const int r = by * 128 + ((i < 4) ? (ty * 4 + i) : (64 + ty * 4 + i - 4));
#pragma unroll
        for (int jg = 0; jg < 2; jg++) {
            const int c = bx * 128 + jg * 64 + tx * 4;
            float4 val;
            val.x = acc[i][jg * 4 + 0]; val.y = acc[i][jg * 4 + 1];
            val.z = acc[i][jg * 4 + 2]; val.w = acc[i][jg * 4 + 3];
            if (PERMUTE) {
                const int h  = c >> 6;        // head
                const int d  = c & 63;        // dim in head (4-aligned)
                const int bb = r >> 11;       // batch (T=2048)
                const int t  = r & 2047;
                *(float4*)&C[(((size_t)(bb * NHEADS + h)) * TSEQ + t) * HD + d] = val;
            } else {
                *(float4*)&C[(size_t)r * 1024 + c] = val;
            }
        }
    }
}

__global__ __launch_bounds__(256) void sgemm_qkv(
    const float* __restrict__ A,
    const float* __restrict__ W0, const float* __restrict__ W1, const float* __restrict__ W2,
    float* __restrict__ C0, float* __restrict__ C1, float* __restrict__ C2)
{
    const float* W = (blockIdx.z == 0) ? W0 : (blockIdx.z == 1) ? W1 : W2;
    float*       C = (blockIdx.z == 0) ? C0 : (blockIdx.z == 1) ? C1 : C2;
    gemm_body<1>(A, W, C);
}

__global__ __launch_bounds__(256) void sgemm_o(
    const float* __restrict__ A, const float* __restrict__ W, float* __restrict__ C)
{
    gemm_body<0>(A, W, C);
}

// ---------------------------------------------------------------------------
// Flash attention (fp32, causal). Block = 64 query rows x 1 (b,h).
// 256 threads: ty = tid>>2 owns query row, tx = tid&3 owns 16 output dims.
// Scores live in registers; row reduction via shfl within 4-lane group.
// KV tiles of 32 keys in shared memory.
// ---------------------------------------------------------------------------
__global__ __launch_bounds__(256) void attn_kernel(
    const float* __restrict__ Q, const float* __restrict__ K,
    const float* __restrict__ V, float* __restrict__ O)
{
    __shared__ float Ks[32][68];
    __shared__ float Vs[32][68];

    const int qt  = blockIdx.x;        // query tile (64 rows)
    const int bh  = blockIdx.y;        // b*H + h
    const int tid = threadIdx.x;
    const int ty  = tid >> 2;          // query row in tile (0..63)
    const int tx  = tid & 3;           // dim group (16 dims)
    const int m   = qt * 64 + ty;      // global query index

    // Q fragment: 16 dims of this row
    float qf[16];
    {
        const float* qb = Q + ((size_t)bh * TSEQ + m) * HD + tx * 16;
        float4 q0 = *(const float4*)(qb + 0);
        float4 q1 = *(const float4*)(qb + 4);
        float4 q2 = *(const float4*)(qb + 8);
        float4 q3 = *(const float4*)(qb + 12);
        qf[0]=q0.x; qf[1]=q0.y; qf[2]=q0.z; qf[3]=q0.w;
        qf[4]=q1.x; qf[5]=q1.y; qf[6]=q1.z; qf[7]=q1.w;
        qf[8]=q2.x; qf[9]=q2.y; qf[10]=q2.z; qf[11]=q2.w;
        qf[12]=q3.x; qf[13]=q3.y; qf[14]=q3.z; qf[15]=q3.w;
    }

    float acc[16];
#pragma unroll
    for (int i = 0; i < 16; i++) acc[i] = 0.f;
    float m_i = -1e30f, l_i = 0.f;

    const int ktiles = 2 * (qt + 1);   // 32-key tiles covering keys <= qt*64+63
    const float scale = 0.125f;        // 1/sqrt(64)

    for (int kt = 0; kt < ktiles; kt++) {
        // Load 32x64 K and V tiles (512 float4 each, 2 per thread)
        {
            const size_t base = ((size_t)bh * TSEQ + kt * 32) * HD;
#pragma unroll
            for (int rr = 0; rr < 2; rr++) {
                const int r  = tid + rr * 256;
                const int n  = r >> 4;
                const int c4 = (r & 15) << 2;
                *(float4*)&Ks[n][c4] = *(const float4*)(K + base + (size_t)n * HD + c4);
                *(float4*)&Vs[n][c4] = *(const float4*)(V + base + (size_t)n * HD + c4);
            }
        }
        __syncthreads();

        // Partial dot products over this thread's 16 dims, all 32 keys
        float s[32];
#pragma unroll
        for (int n = 0; n < 32; n++) {
            const float4 k0 = *(const float4*)(&Ks[n][tx * 16 + 0]);
            const float4 k1 = *(const float4*)(&Ks[n][tx * 16 + 4]);
            const float4 k2 = *(const float4*)(&Ks[n][tx * 16 + 8]);
            const float4 k3 = *(const float4*)(&Ks[n][tx * 16 + 12]);
            float p;
            p = qf[0]*k0.x;          p = fmaf(qf[1],k0.y,p);
            p = fmaf(qf[2],k0.z,p);  p = fmaf(qf[3],k0.w,p);
            p = fmaf(qf[4],k1.x,p);  p = fmaf(qf[5],k1.y,p);
            p = fmaf(qf[6],k1.z,p);  p = fmaf(qf[7],k1.w,p);
            p = fmaf(qf[8],k2.x,p);  p = fmaf(qf[9],k2.y,p);
            p = fmaf(qf[10],k2.z,p); p = fmaf(qf[11],k2.w,p);
            p = fmaf(qf[12],k3.x,p); p = fmaf(qf[13],k3.y,p);
            p = fmaf(qf[14],k3.z,p); p = fmaf(qf[15],k3.w,p);
            s[n] = p;
        }

        // Reduce across the 4 lanes of this row; apply scale + causal mask
        float tmax = -1e30f;
#pragma unroll
        for (int n = 0; n < 32; n++) {
            float v = s[n];
            v += __shfl_xor_sync(0xffffffffu, v, 1);
            v += __shfl_xor_sync(0xffffffffu, v, 2);
            v *= scale;
            const int key = kt * 32 + n;
            if (key > m) v = -1e30f;
            s[n] = v;
            tmax = fmaxf(tmax, v);
        }

        const float m_new = fmaxf(m_i, tmax);
        const float corr  = __expf(m_i - m_new);
        float psum = 0.f;
#pragma unroll
        for (int n = 0; n < 32; n++) {
            s[n] = __expf(s[n] - m_new);
            psum += s[n];
        }
        l_i = l_i * corr + psum;
        m_i = m_new;
#pragma unroll
        for (int i = 0; i < 16; i++) acc[i] *= corr;

        // acc += P @ V over this thread's 16 dims
#pragma unroll
        for (int n = 0; n < 32; n++) {
            const float p = s[n];
            const float4 v0 = *(const float4*)(&Vs[n][tx * 16 + 0]);
            const float4 v1 = *(const float4*)(&Vs[n][tx * 16 + 4]);
            const float4 v2 = *(const float4*)(&Vs[n][tx * 16 + 8]);
            const float4 v3 = *(const float4*)(&Vs[n][tx * 16 + 12]);
            acc[0]  = fmaf(p, v0.x, acc[0]);  acc[1]  = fmaf(p, v0.y, acc[1]);
            acc[2]  = fmaf(p, v0.z, acc[2]);  acc[3]  = fmaf(p, v0.w, acc[3]);
            acc[4]  = fmaf(p, v1.x, acc[4]);  acc[5]  = fmaf(p, v1.y, acc[5]);
            acc[6]  = fmaf(p, v1.z, acc[6]);  acc[7]  = fmaf(p, v1.w, acc[7]);
            acc[8]  = fmaf(p, v2.x, acc[8]);  acc[9]  = fmaf(p, v2.y, acc[9]);
            acc[10] = fmaf(p, v2.z, acc[10]); acc[11] = fmaf(p, v2.w, acc[11]);
            acc[12] = fmaf(p, v3.x, acc[12]); acc[13] = fmaf(p, v3.y, acc[13]);
            acc[14] = fmaf(p, v3.z, acc[14]); acc[15] = fmaf(p, v3.w, acc[15]);
        }
        __syncthreads();
    }

    // Normalize and write to [B,T,H*64] layout
    const float inv = 1.f / l_i;
    const int bb = bh >> 4;
    const int h  = bh & 15;
    float* ob = O + ((size_t)(bb * TSEQ + m)) * D_MODEL + h * HD + tx * 16;
    float4 o0, o1, o2, o3;
    o0.x=acc[0]*inv;  o0.y=acc[1]*inv;  o0.z=acc[2]*inv;  o0.w=acc[3]*inv;
    o1.x=acc[4]*inv;  o1.y=acc[5]*inv;  o1.z=acc[6]*inv;  o1.w=acc[7]*inv;
    o2.x=acc[8]*inv;  o2.y=acc[9]*inv;  o2.z=acc[10]*inv; o2.w=acc[11]*inv;
    o3.x=acc[12]*inv; o3.y=acc[13]*inv; o3.z=acc[14]*inv; o3.w=acc[15]*inv;
    *(float4*)(ob + 0)  = o0;
    *(float4*)(ob + 4)  = o1;
    *(float4*)(ob + 8)  = o2;
    *(float4*)(ob + 12) = o3;
}

// ---------------------------------------------------------------------------
extern "C" void kernel_launch(void* const* d_in, const int* in_sizes, int n_in,
                              void* d_out, int out_size)
{
    const float* x  = (const float*)d_in[0];
    const float* Wq = (const float*)d_in[1];
    const float* Wk = (const float*)d_in[2];
    const float* Wv = (const float*)d_in[3];
    const float* Wo = (const float*)d_in[4];
    float* out = (float*)d_out;

    float *q, *k, *v, *attn;
    cudaGetSymbolAddress((void**)&q,    g_q);
    cudaGetSymbolAddress((void**)&k,    g_k);
    cudaGetSymbolAddress((void**)&v,    g_v);
    cudaGetSymbolAddress((void**)&attn, g_attn);

    dim3 gqkv(1024 / 128, MROWS / 128, 3);
    sgemm_qkv<<<gqkv, 256>>>(x, Wq, Wk, Wv, q, k, v);

    dim3 gattn(TSEQ / 64, BATCH * NHEADS);
    attn_kernel<<<gattn, 256>>>(q, k, v, attn);

    dim3 go(1024 / 128, MROWS / 128);
    sgemm_o<<<go, 256>>>(attn, Wo, out);
}

// round 2
// speedup vs baseline: 5.2677x; 5.2677x over previous
#include <cuda_runtime.h>
#include <cstddef>

#define D_MODEL 1024
#define NHEADS  16
#define HD      64
#define BATCH   2
#define TSEQ    2048
#define MROWS   (BATCH*TSEQ)   /* 4096 */

// Scratch buffers (device globals: no allocations allowed)
__device__ float g_q[(size_t)MROWS * D_MODEL];     // [B,H,T,64]
__device__ float g_k[(size_t)MROWS * D_MODEL];     // [B,H,T,64]
__device__ float g_v[(size_t)MROWS * D_MODEL];     // [B,H,T,64]
__device__ float g_attn[(size_t)MROWS * D_MODEL];  // [B,T,1024]

// ---------------------------------------------------------------------------
// helpers
// ---------------------------------------------------------------------------
__device__ __forceinline__ unsigned f2tf32(float x) {
    unsigned r;
    asm("cvt.rna.tf32.f32 %0, %1;" : "=r"(r) : "f"(x));
    return r;
}

__device__ __forceinline__ void mma_tf32(float c[4], const unsigned a[4], const unsigned b[2]) {
    asm volatile(
        "mma.sync.aligned.m16n8k8.row.col.f32.tf32.tf32.f32 "
        "{%0,%1,%2,%3}, {%4,%5,%6,%7}, {%8,%9}, {%0,%1,%2,%3};"
        : "+f"(c[0]), "+f"(c[1]), "+f"(c[2]), "+f"(c[3])
        : "r"(a[0]), "r"(a[1]), "r"(a[2]), "r"(a[3]), "r"(b[0]), "r"(b[1]));
}

// fast exp2 for x <= 0 (FMA pipe, no MUFU)
__device__ __forceinline__ float exp2p(float x) {
    x = fmaxf(x, -126.f);
    float z = x + 12582912.0f;            // 1.5*2^23: round-to-nearest-int trick
    int   n = __float_as_int(z) - 0x4B400000;
    float f = x - (z - 12582912.0f);      // f in [-0.5, 0.5]
    float p = 0.0096181291f;
    p = fmaf(p, f, 0.0555041087f);
    p = fmaf(p, f, 0.2402265069f);
    p = fmaf(p, f, 0.6931471806f);
    p = fmaf(p, f, 1.0f);
    return __int_as_float(__float_as_int(p) + (n << 23));
}

// ---------------------------------------------------------------------------
// tf32 tensor-core GEMM: C = A @ W^T
// A [4096,1024] row-major fp32, W [1024,1024] row-major fp32.
// 128x128x32 tiles, 256 threads = 8 warps, warp tile 32x64 (2 m16 x 8 n8).
// PERMUTE=1: scatter C[r][c] into [B,H,T,64] layout.
// ---------------------------------------------------------------------------
template <int PERMUTE>
__device__ __forceinline__ void gemm_tc_body(const float* __restrict__ A,
                                             const float* __restrict__ W,
                                             float* __restrict__ C)
{
    __shared__ float As[128][36];   // [m][k]  (tf32 bit patterns)
    __shared__ float Bs[128][36];   // [n][k]

    const int tid  = threadIdx.x;
    const int lane = tid & 31;
    const int warp = tid >> 5;
    const int wm   = warp >> 1;          // 0..3
    const int wn   = warp & 1;           // 0..1
    const int bx   = blockIdx.x;
    const int by   = blockIdx.y;
    const int r4   = lane >> 2;          // 0..7
    const int c4   = lane & 3;           // 0..3

    const int lr = tid >> 1;             // 0..127
    const int lc = (tid & 1) * 16;       // 0 or 16
    const float* Ag = A + (size_t)(by * 128 + lr) * 1024 + lc;
    const float* Wg = W + (size_t)(bx * 128 + lr) * 1024 + lc;

    float acc[2][8][4];
#pragma unroll
    for (int mt = 0; mt < 2; mt++)
#pragma unroll
        for (int nt = 0; nt < 8; nt++)
#pragma unroll
            for (int i = 0; i < 4; i++) acc[mt][nt][i] = 0.f;

    for (int k0 = 0; k0 < 1024; k0 += 32) {
        float4 a[4], b[4];
#pragma unroll
        for (int i = 0; i < 4; i++) {
            a[i] = *(const float4*)(Ag + k0 + i * 4);
            b[i] = *(const float4*)(Wg + k0 + i * 4);
        }
        __syncthreads();
#pragma unroll
        for (int i = 0; i < 4; i++) {
            As[lr][lc + i*4 + 0] = __uint_as_float(f2tf32(a[i].x));
            As[lr][lc + i*4 + 1] = __uint_as_float(f2tf32(a[i].y));
            As[lr][lc + i*4 + 2] = __uint_as_float(f2tf32(a[i].z));
            As[lr][lc + i*4 + 3] = __uint_as_float(f2tf32(a[i].w));
            Bs[lr][lc + i*4 + 0] = __uint_as_float(f2tf32(b[i].x));
            Bs[lr][lc + i*4 + 1] = __uint_as_float(f2tf32(b[i].y));
            Bs[lr][lc + i*4 + 2] = __uint_as_float(f2tf32(b[i].z));
            Bs[lr][lc + i*4 + 3] = __uint_as_float(f2tf32(b[i].w));
        }
        __syncthreads();

#pragma unroll
        for (int ks = 0; ks < 4; ks++) {
            unsigned af[2][4];
#pragma unroll
            for (int mt = 0; mt < 2; mt++) {
                const int r = wm * 32 + mt * 16 + r4;
                af[mt][0] = __float_as_uint(As[r    ][ks*8 + c4    ]);
                af[mt][1] = __float_as_uint(As[r + 8][ks*8 + c4    ]);
                af[mt][2] = __float_as_uint(As[r    ][ks*8 + c4 + 4]);
                af[mt][3] = __float_as_uint(As[r + 8][ks*8 + c4 + 4]);
            }
#pragma unroll
            for (int nt = 0; nt < 8; nt++) {
                const int n = wn * 64 + nt * 8 + r4;
                unsigned bf[2];
                bf[0] = __float_as_uint(Bs[n][ks*8 + c4    ]);
                bf[1] = __float_as_uint(Bs[n][ks*8 + c4 + 4]);
                mma_tf32(acc[0][nt], af[0], bf);
                mma_tf32(acc[1][nt], af[1], bf);
            }
        }
    }

#pragma unroll
    for (int mt = 0; mt < 2; mt++) {
        const int r0 = by * 128 + wm * 32 + mt * 16 + r4;
#pragma unroll
        for (int nt = 0; nt < 8; nt++) {
            const int c = bx * 128 + wn * 64 + nt * 8 + 2 * c4;
            float2 v0 = make_float2(acc[mt][nt][0], acc[mt][nt][1]);
            float2 v1 = make_float2(acc[mt][nt][2], acc[mt][nt][3]);
            if (PERMUTE) {
                const int h  = c >> 6;
                const int d  = c & 63;
                const int bb = r0 >> 11;
                const int t0 = r0 & 2047;
                const int t1 = (r0 + 8) & 2047;
                *(float2*)&C[(((size_t)(bb * NHEADS + h)) * TSEQ + t0) * HD + d] = v0;
                *(float2*)&C[(((size_t)(bb * NHEADS + h)) * TSEQ + t1) * HD + d] = v1;
            } else {
                *(float2*)&C[(size_t)r0 * 1024 + c]       = v0;
                *(float2*)&C[(size_t)(r0 + 8) * 1024 + c] = v1;
            }
        }
    }
}

__global__ __launch_bounds__(256) void gemm_qkv_tc(
    const float* __restrict__ A,
    const float* __restrict__ W0, const float* __restrict__ W1, const float* __restrict__ W2,
    float* __restrict__ C0, float* __restrict__ C1, float* __restrict__ C2)
{
    const float* W = (blockIdx.z == 0) ? W0 : (blockIdx.z == 1) ? W1 : W2;
    float*       C = (blockIdx.z == 0) ? C0 : (blockIdx.z == 1) ? C1 : C2;
    gemm_tc_body<1>(A, W, C);
}

__global__ __launch_bounds__(256) void gemm_o_tc(
    const float* __restrict__ A, const float* __restrict__ W, float* __restrict__ C)
{
    gemm_tc_body<0>(A, W, C);
}

// ---------------------------------------------------------------------------
// Flash attention, tf32 tensor cores, causal.
// Block: 128 threads (4 warps) handles 64 query rows of one (b,h).
// Warp w owns q rows [w*16, w*16+16). K tiles of 64 keys.
// Q fragments in registers; K [key][d] and V transposed [d][key] in smem;
// P goes through per-warp smem to re-fragment for the PV mma.
// Softmax in base-2 domain with FMA-pipe exp2 polynomial (no MUFU).
// ---------------------------------------------------------------------------
#define ATTN_PAD 68
#define ATTN_SMEM_FLOATS (64*ATTN_PAD /*K*/ + 64*ATTN_PAD /*V*/ + 4*16*ATTN_PAD /*P*/)

__global__ __launch_bounds__(128) void attn_tc(
    const float* __restrict__ Q, const float* __restrict__ K,
    const float* __restrict__ V, float* __restrict__ O)
{
    extern __shared__ float sm[];
    float* Ks = sm;                       // [64][68]  (key-major)
    float* Vs = sm + 64 * ATTN_PAD;       // [64][68]  (dim-major, transposed)
    float* Pb = sm + 128 * ATTN_PAD;      // [4][16][68]

    const int tid  = threadIdx.x;
    const int lane = tid & 31;
    const int w    = tid >> 5;
    const int r4   = lane >> 2;           // 0..7
    const int c4   = lane & 3;            // 0..3
    const int bh   = blockIdx.y;
    const int qt   = (int)gridDim.x - 1 - (int)blockIdx.x;   // heavy blocks first

    float* Psw = Pb + w * 16 * ATTN_PAD;

    // Q fragments (register resident, tf32)
    unsigned qf[8][4];
    {
        const float* Qb = Q + ((size_t)bh * TSEQ + qt * 64 + w * 16) * HD;
#pragma unroll
        for (int ks = 0; ks < 8; ks++) {
            qf[ks][0] = f2tf32(Qb[(r4    ) * HD + ks*8 + c4    ]);
            qf[ks][1] = f2tf32(Qb[(r4 + 8) * HD + ks*8 + c4    ]);
            qf[ks][2] = f2tf32(Qb[(r4    ) * HD + ks*8 + c4 + 4]);
            qf[ks][3] = f2tf32(Qb[(r4 + 8) * HD + ks*8 + c4 + 4]);
        }
    }

    float oacc[8][4];
#pragma unroll
    for (int dt = 0; dt < 8; dt++)
#pragma unroll
        for (int i = 0; i < 4; i++) oacc[dt][i] = 0.f;
    float rm0 = -1e30f, rm1 = -1e30f, rl0 = 0.f, rl1 = 0.f;

    const int rowL0 = w * 16 + r4;
    const int rowL1 = rowL0 + 8;
    const float SC2 = 0.1803368801f;      // (1/8) * log2(e)

    for (int kt = 0; kt <= qt; kt++) {
        __syncthreads();
        {
            const float* Kb = K + ((size_t)bh * TSEQ + kt * 64) * HD;
            const float* Vb = V + ((size_t)bh * TSEQ + kt * 64) * HD;
#pragma unroll
            for (int j = 0; j < 8; j++) {
                const int f   = tid + 128 * j;
                const int row = f >> 4;
                const int cc  = (f & 15) << 2;
                float4 kv = *(const float4*)(Kb + row * HD + cc);
                Ks[row * ATTN_PAD + cc + 0] = __uint_as_float(f2tf32(kv.x));
                Ks[row * ATTN_PAD + cc + 1] = __uint_as_float(f2tf32(kv.y));
                Ks[row * ATTN_PAD + cc + 2] = __uint_as_float(f2tf32(kv.z));
                Ks[row * ATTN_PAD + cc + 3] = __uint_as_float(f2tf32(kv.w));
                float4 vv = *(const float4*)(Vb + row * HD + cc);
                Vs[(cc + 0) * ATTN_PAD + row] = __uint_as_float(f2tf32(vv.x));
                Vs[(cc + 1) * ATTN_PAD + row] = __uint_as_float(f2tf32(vv.y));
                Vs[(cc + 2) * ATTN_PAD + row] = __uint_as_float(f2tf32(vv.z));
                Vs[(cc + 3) * ATTN_PAD + row] = __uint_as_float(f2tf32(vv.w));
            }
        }
        __syncthreads();

        // S = Q @ K^T  (per warp: 16 x 64)
        float sf[8][4];
#pragma unroll
        for (int nt = 0; nt < 8; nt++) {
            sf[nt][0] = sf[nt][1] = sf[nt][2] = sf[nt][3] = 0.f;
#pragma unroll
            for (int ks = 0; ks < 8; ks++) {
                unsigned bf[2];
                const int key = nt * 8 + r4;
                bf[0] = __float_as_uint(Ks[key * ATTN_PAD + ks*8 + c4    ]);
                bf[1] = __float_as_uint(Ks[key * ATTN_PAD + ks*8 + c4 + 4]);
                mma_tf32(sf[nt], qf[ks], bf);
            }
        }

        // scale to log2 domain + causal mask (diagonal tile only)
        const bool diag = (kt == qt);
#pragma unroll
        for (int nt = 0; nt < 8; nt++) {
            sf[nt][0] *= SC2; sf[nt][1] *= SC2; sf[nt][2] *= SC2; sf[nt][3] *= SC2;
            if (diag) {
                const int kc = nt * 8 + 2 * c4;
                if (kc     > rowL0) sf[nt][0] = -1e30f;
                if (kc + 1 > rowL0) sf[nt][1] = -1e30f;
                if (kc     > rowL1) sf[nt][2] = -1e30f;
                if (kc + 1 > rowL1) sf[nt][3] = -1e30f;
            }
        }

        // row max
        float mx0 = -1e30f, mx1 = -1e30f;
#pragma unroll
        for (int nt = 0; nt < 8; nt++) {
            mx0 = fmaxf(mx0, fmaxf(sf[nt][0], sf[nt][1]));
            mx1 = fmaxf(mx1, fmaxf(sf[nt][2], sf[nt][3]));
        }
        mx0 = fmaxf(mx0, __shfl_xor_sync(0xffffffffu, mx0, 1));
        mx0 = fmaxf(mx0, __shfl_xor_sync(0xffffffffu, mx0, 2));
        mx1 = fmaxf(mx1, __shfl_xor_sync(0xffffffffu, mx1, 1));
        mx1 = fmaxf(mx1, __shfl_xor_sync(0xffffffffu, mx1, 2));

        const float nm0 = fmaxf(rm0, mx0), nm1 = fmaxf(rm1, mx1);
        const float corr0 = exp2p(rm0 - nm0), corr1 = exp2p(rm1 - nm1);
        rm0 = nm0; rm1 = nm1;

        float s0 = 0.f, s1 = 0.f;
#pragma unroll
        for (int nt = 0; nt < 8; nt++) {
            const float p0 = exp2p(sf[nt][0] - nm0);
            const float p1 = exp2p(sf[nt][1] - nm0);
            const float p2 = exp2p(sf[nt][2] - nm1);
            const float p3 = exp2p(sf[nt][3] - nm1);
            s0 += p0 + p1;  s1 += p2 + p3;
            const int col = nt * 8 + 2 * c4;
            Psw[(r4    ) * ATTN_PAD + col    ] = __uint_as_float(f2tf32(p0));
            Psw[(r4    ) * ATTN_PAD + col + 1] = __uint_as_float(f2tf32(p1));
            Psw[(r4 + 8) * ATTN_PAD + col    ] = __uint_as_float(f2tf32(p2));
            Psw[(r4 + 8) * ATTN_PAD + col + 1] = __uint_as_float(f2tf32(p3));
        }
        s0 += __shfl_xor_sync(0xffffffffu, s0, 1);
        s0 += __shfl_xor_sync(0xffffffffu, s0, 2);
        s1 += __shfl_xor_sync(0xffffffffu, s1, 1);
        s1 += __shfl_xor_sync(0xffffffffu, s1, 2);
        rl0 = rl0 * corr0 + s0;
        rl1 = rl1 * corr1 + s1;

#pragma unroll
        for (int dt = 0; dt < 8; dt++) {
            oacc[dt][0] *= corr0; oacc[dt][1] *= corr0;
            oacc[dt][2] *= corr1; oacc[dt][3] *= corr1;
        }
        __syncwarp();

        // O += P @ V   (k = keys, n = dims; V stored dim-major)
#pragma unroll
        for (int ks = 0; ks < 8; ks++) {
            unsigned pf[4];
            pf[0] = __float_as_uint(Psw[(r4    ) * ATTN_PAD + ks*8 + c4    ]);
            pf[1] = __float_as_uint(Psw[(r4 + 8) * ATTN_PAD + ks*8 + c4    ]);
            pf[2] = __float_as_uint(Psw[(r4    ) * ATTN_PAD + ks*8 + c4 + 4]);
            pf[3] = __float_as_uint(Psw[(r4 + 8) * ATTN_PAD + ks*8 + c4 + 4]);
#pragma unroll
            for (int dt = 0; dt < 8; dt++) {
                unsigned bf[2];
                const int dim = dt * 8 + r4;
                bf[0] = __float_as_uint(Vs[dim * ATTN_PAD + ks*8 + c4    ]);
                bf[1] = __float_as_uint(Vs[dim * ATTN_PAD + ks*8 + c4 + 4]);
                mma_tf32(oacc[dt], pf, bf);
            }
        }
    }

    // epilogue: normalize, write [B,T,1024]
    const float inv0 = 1.f / rl0;
    const float inv1 = 1.f / rl1;
    const int bb = bh >> 4;
    const int h  = bh & 15;
    const size_t rg = (size_t)(bb * TSEQ + qt * 64 + w * 16 + r4);
    float* O0 = O + rg * D_MODEL + h * HD;
    float* O1 = O + (rg + 8) * D_MODEL + h * HD;
#pragma unroll
    for (int dt = 0; dt < 8; dt++) {
        const int dim = dt * 8 + 2 * c4;
        *(float2*)(O0 + dim) = make_float2(oacc[dt][0] * inv0, oacc[dt][1] * inv0);
        *(float2*)(O1 + dim) = make_float2(oacc[dt][2] * inv1, oacc[dt][3] * inv1);
    }
}

// ---------------------------------------------------------------------------
extern "C" void kernel_launch(void* const* d_in, const int* in_sizes, int n_in,
                              void* d_out, int out_size)
{
    const float* x  = (const float*)d_in[0];
    const float* Wq = (const float*)d_in[1];
    const float* Wk = (const float*)d_in[2];
    const float* Wv = (const float*)d_in[3];
    const float* Wo = (const float*)d_in[4];
    float* out = (float*)d_out;

    float *q, *k, *v, *attn;
    cudaGetSymbolAddress((void**)&q,    g_q);
    cudaGetSymbolAddress((void**)&k,    g_k);
    cudaGetSymbolAddress((void**)&v,    g_v);
    cudaGetSymbolAddress((void**)&attn, g_attn);

    const int attn_smem = ATTN_SMEM_FLOATS * (int)sizeof(float);
    cudaFuncSetAttribute(attn_tc, cudaFuncAttributeMaxDynamicSharedMemorySize, attn_smem);

    dim3 gqkv(1024 / 128, MROWS / 128, 3);
    gemm_qkv_tc<<<gqkv, 256>>>(x, Wq, Wk, Wv, q, k, v);

    dim3 gattn(TSEQ / 64, BATCH * NHEADS);
    attn_tc<<<gattn, 128, attn_smem>>>(q, k, v, attn);

    dim3 go(1024 / 128, MROWS / 128);
    gemm_o_tc<<<go, 256>>>(attn, Wo, out);
}